// round 7
// baseline (speedup 1.0000x reference)
#include <cuda_runtime.h>

// CostVolume: left,right [B,C,H,W] f32 -> out [B,2C,D,H,W] f32
//   out[b, c,      d, h, w] = (w+d < W) ? left [b,c,h,w+d] : 0
//   out[b, C + c,  d, h, w] = (w-d >= 0)? right[b,c,h,w-d] : 0
//
// Fixed shapes: B=2, C=32, H=128, W=256, D=32.
//
// R7: Blackwell 256-bit stores. Each thread owns one 8-float output column
// (w8) and 16 disparities: loads a 24-float register window (6 x LDS.128)
// from a zero-padded smem row once, then emits one uninterrupted burst of
// 16 x st.global.cs.v8.f32 (STG.256). Warp store wavefront = 1024 B
// contiguous. 256-thread CTA covers 2 h-rows (grid 4096).
// Mapping per 128-thread row group:
//   half = (t128>>6)&1, dhalf = (t128>>5)&1, t32 = t128&31, w8 = 8*t32.

namespace {
constexpr int B = 2;
constexpr int C = 32;
constexpr int H = 128;
constexpr int W = 256;
constexpr int D = 32;
constexpr int PADQ = 72;   // float4s per padded row buffer (288 floats)
}

__device__ __forceinline__ void stcs256(float* p, const float* v) {
    asm volatile(
        "st.global.cs.v8.f32 [%0], {%1,%2,%3,%4,%5,%6,%7,%8};"
        :: "l"(p),
           "f"(v[0]), "f"(v[1]), "f"(v[2]), "f"(v[3]),
           "f"(v[4]), "f"(v[5]), "f"(v[6]), "f"(v[7])
        : "memory");
}

__global__ __launch_bounds__(256)
void cost_volume_kernel(const float* __restrict__ left,
                        const float* __restrict__ right,
                        float* __restrict__ out) {
    // Per row r (0..1):
    //   slbuf[r] floats: [0..255] = left row, [256..287] = zero tail.
    //   srbuf[r] floats: [0..31] = zero head, [32..287] = right row
    //                    (srbuf float j holds right_row[j-32]).
    __shared__ float4 slbuf[2][PADQ];
    __shared__ float4 srbuf[2][PADQ];

    const int blk = blockIdx.x;            // b*C*(H/2) + c*(H/2) + hp
    const int hp = blk & (H / 2 - 1);      // 64 row pairs per (b,c)
    const int c  = (blk >> 6) & (C - 1);
    const int b  = blk >> 11;

    const int tid   = threadIdx.x;         // 0..255
    const int rsub  = tid >> 7;            // row within pair
    const int t128  = tid & 127;
    const int half  = t128 >> 6;           // 0 = left, 1 = right
    const int dhalf = (t128 >> 5) & 1;     // d block
    const int t32   = t128 & 31;           // float8 column
    const int w8    = t32 << 3;
    const int d0    = dhalf << 4;          // 0 or 16
    const int h     = hp * 2 + rsub;

    const size_t in_off = ((((size_t)b * C + c) * H) + h) * W;

    // ---- stage row pair + zero pads (per 128-thread row group) ----
    if (t128 < 64) {
        slbuf[rsub][t128] = reinterpret_cast<const float4*>(left + in_off)[t128];
    } else {
        srbuf[rsub][8 + (t128 - 64)] =
            reinterpret_cast<const float4*>(right + in_off)[t128 - 64];
    }
    if (tid < 16) {
        const int r = tid >> 3;            // 0..1
        const int q = tid & 7;             // 0..7
        slbuf[r][64 + q] = make_float4(0.f, 0.f, 0.f, 0.f);
        srbuf[r][q]      = make_float4(0.f, 0.f, 0.f, 0.f);
    }
    __syncthreads();

    // ---- 24-float register window (6 x LDS.128) ----
    // Left  thread: f[k] = left_row [w8 + d0 + k],      k = 0..23
    //   -> slbuf float4 base = 2*t32 + d0/4
    // Right thread: f[k] = right_row[w8 - d0 - 16 + k], k = 0..23
    //   -> srbuf float4 base = (w8 - d0 - 16 + 32)/4 = 2*t32 - d0/4 + 4
    float f[24];
    {
        const float4* buf  = half ? srbuf[rsub] : slbuf[rsub];
        const int     base = half ? (2 * t32 - 4 * dhalf + 4)
                                  : (2 * t32 + 4 * dhalf);
        #pragma unroll
        for (int i = 0; i < 6; i++) {
            float4 q = buf[base + i];
            f[4 * i + 0] = q.x;
            f[4 * i + 1] = q.y;
            f[4 * i + 2] = q.z;
            f[4 * i + 3] = q.w;
        }
    }

    // ---- emit 16 disparity planes: one burst of STG.256 ----
    const size_t dstride = (size_t)H * W;  // 32768 floats per d-plane
    float* dst = out
        + ((size_t)(b * 2 * C + half * C + c) * D + d0) * dstride
        + (size_t)h * W + w8;

    if (half == 0) {
        // d = d0 + dd: out = left_row[w8+d .. w8+d+7] = f[dd .. dd+7]
        #pragma unroll
        for (int dd = 0; dd < 16; dd++) {
            stcs256(dst + (size_t)dd * dstride, &f[dd]);
        }
    } else {
        // d = d0 + dd: out = right_row[w8-d .. w8-d+7] = f[16-dd .. 23-dd]
        #pragma unroll
        for (int dd = 0; dd < 16; dd++) {
            stcs256(dst + (size_t)dd * dstride, &f[16 - dd]);
        }
    }
}

extern "C" void kernel_launch(void* const* d_in, const int* in_sizes, int n_in,
                              void* d_out, int out_size) {
    const float* left  = (const float*)d_in[0];
    const float* right = (const float*)d_in[1];
    float* out = (float*)d_out;

    (void)in_sizes; (void)n_in; (void)out_size;

    const int grid = B * C * (H / 2);  // 4096 CTAs
    cost_volume_kernel<<<grid, 256>>>(left, right, out);
}

// round 8
// speedup vs baseline: 1.0004x; 1.0004x over previous
#include <cuda_runtime.h>

// CostVolume: left,right [B,C,H,W] f32 -> out [B,2C,D,H,W] f32
//   out[b, c,      d, h, w] = (w+d < W) ? left [b,c,h,w+d] : 0
//   out[b, C + c,  d, h, w] = (w-d >= 0)? right[b,c,h,w-d] : 0
//
// Fixed shapes: B=2, C=32, H=128, W=256, D=32.
//
// R8: identical to R6 (best: 76.3us) except output stores use st.global.wt
// (write-through) instead of st.global.cs. The 536 MB output is write-once;
// write-through avoids dirty-L2-line accumulation/writeback bursts on the
// pure store stream. Structure: 512-thread CTA covers 2 h-rows (grid 4096);
// per thread: 5 x LDS.128 zero-padded window -> one uninterrupted burst of
// 16 x STG.128.

namespace {
constexpr int B = 2;
constexpr int C = 32;
constexpr int H = 128;
constexpr int W = 256;
constexpr int D = 32;
constexpr int PADQ = 72;   // float4s per padded row buffer
}

__device__ __forceinline__ void stwt128(float* p, float4 v) {
    asm volatile(
        "st.global.wt.v4.f32 [%0], {%1,%2,%3,%4};"
        :: "l"(p), "f"(v.x), "f"(v.y), "f"(v.z), "f"(v.w)
        : "memory");
}

__global__ __launch_bounds__(512)
void cost_volume_kernel(const float* __restrict__ left,
                        const float* __restrict__ right,
                        float* __restrict__ out) {
    // Per row r (0..1):
    //   slbuf[r] floats: [0..255] = left row, [256..287] = zero tail.
    //   srbuf[r] floats: [0..31] = zero head, [32..287] = right row.
    __shared__ float4 slbuf[2][PADQ];
    __shared__ float4 srbuf[2][PADQ];

    const int blk = blockIdx.x;            // b*C*(H/2) + c*(H/2) + hp
    const int hp = blk & (H / 2 - 1);      // 64 row pairs per (b,c)
    const int c  = (blk >> 6) & (C - 1);
    const int b  = blk >> 11;

    const int tid   = threadIdx.x;         // 0..511
    const int rsub  = tid >> 8;            // row within pair
    const int t256  = tid & 255;
    const int half  = t256 >> 7;           // 0 = left, 1 = right
    const int dhalf = (t256 >> 6) & 1;     // d block
    const int l64   = t256 & 63;           // float4 column
    const int w4    = l64 << 2;
    const int d0    = dhalf << 4;          // 0 or 16
    const int h     = hp * 2 + rsub;

    const size_t in_off = ((((size_t)b * C + c) * H) + h) * W;

    // ---- stage row pair + zero pads (per 256-thread group) ----
    if (t256 < 64) {
        slbuf[rsub][t256] = reinterpret_cast<const float4*>(left + in_off)[t256];
    } else if (t256 < 128) {
        srbuf[rsub][8 + (t256 - 64)] =
            reinterpret_cast<const float4*>(right + in_off)[t256 - 64];
    } else if (t256 < 136) {
        slbuf[rsub][64 + (t256 - 128)] = make_float4(0.f, 0.f, 0.f, 0.f);
    } else if (t256 < 144) {
        srbuf[rsub][t256 - 136] = make_float4(0.f, 0.f, 0.f, 0.f);
    }
    __syncthreads();

    // ---- 20-float register window (5 x LDS.128) ----
    float f[20];
    {
        const float4* buf  = half ? srbuf[rsub] : slbuf[rsub];
        const int     base = half ? (l64 + 4 - 4 * dhalf) : (l64 + 4 * dhalf);
        #pragma unroll
        for (int i = 0; i < 5; i++) {
            float4 q = buf[base + i];
            f[4 * i + 0] = q.x;
            f[4 * i + 1] = q.y;
            f[4 * i + 2] = q.z;
            f[4 * i + 3] = q.w;
        }
    }

    // ---- emit 16 disparity planes (one uninterrupted write-through burst) ----
    const size_t dstride = (size_t)H * W;  // 32768 floats per d-plane
    float* dst = out
        + ((size_t)(b * 2 * C + half * C + c) * D + d0) * dstride
        + (size_t)h * W + w4;

    if (half == 0) {
        // d = d0 + dd: out = left_row[w4+d .. w4+d+3] = f[dd .. dd+3]
        #pragma unroll
        for (int dd = 0; dd < 16; dd++) {
            float4 v = make_float4(f[dd], f[dd + 1], f[dd + 2], f[dd + 3]);
            stwt128(dst + (size_t)dd * dstride, v);
        }
    } else {
        // d = d0 + dd: out = right_row[w4-d .. w4-d+3] = f[16-dd .. 19-dd]
        #pragma unroll
        for (int dd = 0; dd < 16; dd++) {
            float4 v = make_float4(f[16 - dd], f[17 - dd], f[18 - dd], f[19 - dd]);
            stwt128(dst + (size_t)dd * dstride, v);
        }
    }
}

extern "C" void kernel_launch(void* const* d_in, const int* in_sizes, int n_in,
                              void* d_out, int out_size) {
    const float* left  = (const float*)d_in[0];
    const float* right = (const float*)d_in[1];
    float* out = (float*)d_out;

    (void)in_sizes; (void)n_in; (void)out_size;

    const int grid = B * C * (H / 2);  // 4096 CTAs
    cost_volume_kernel<<<grid, 512>>>(left, right, out);
}

// round 9
// speedup vs baseline: 1.0868x; 1.0864x over previous
#include <cuda_runtime.h>

// CostVolume: left,right [B,C,H,W] f32 -> out [B,2C,D,H,W] f32
//   out[b, c,      d, h, w] = (w+d < W) ? left [b,c,h,w+d] : 0
//   out[b, C + c,  d, h, w] = (w-d >= 0)? right[b,c,h,w-d] : 0
//
// Fixed shapes: B=2, C=32, H=128, W=256, D=32.
//
// FINAL (R6 re-land, measured best 76.3us = ~7.25 TB/s effective, ~91% of
// HBM3e spec). Design, validated by 8 rounds of ncu evidence:
//   - One 512-thread CTA per pair of adjacent h rows (grid 4096).
//   - Rows staged once in zero-padded smem (pads encode the boundary zeros,
//     so the store path has no conditionals).
//   - Each thread loads a 20-float register window (5 x LDS.128) covering
//     its 4-float output column across its 16 disparities, then emits one
//     uninterrupted burst of 16 x STG.128 with st.global.cs (evict-first;
//     keeps L2 write aggregation but avoids dirty-line retention of the
//     536 MB write-once stream). LDS traffic = 7% of store traffic.
//   - Measured dead ends: .wt (loses L2 write combining, +8us), STG.256
//     (sliding window forces per-store octet rebuilds, regs 38->54, +8us),
//     4-row fusion with interleaved reload (breaks burst, +6us), higher
//     occupancy (BW flat across occ 45%->69% => not latency-bound).

namespace {
constexpr int B = 2;
constexpr int C = 32;
constexpr int H = 128;
constexpr int W = 256;
constexpr int D = 32;
constexpr int PADQ = 72;   // float4s per padded row buffer
}

__device__ __forceinline__ void stcs128(float* p, float4 v) {
    __stcs(reinterpret_cast<float4*>(p), v);
}

__global__ __launch_bounds__(512)
void cost_volume_kernel(const float* __restrict__ left,
                        const float* __restrict__ right,
                        float* __restrict__ out) {
    // Per row r (0..1):
    //   slbuf[r] floats: [0..255] = left row, [256..287] = zero tail.
    //   srbuf[r] floats: [0..31] = zero head, [32..287] = right row
    //                    (srbuf float j holds right_row[j-32]).
    __shared__ float4 slbuf[2][PADQ];
    __shared__ float4 srbuf[2][PADQ];

    const int blk = blockIdx.x;            // b*C*(H/2) + c*(H/2) + hp
    const int hp = blk & (H / 2 - 1);      // 64 row pairs per (b,c)
    const int c  = (blk >> 6) & (C - 1);
    const int b  = blk >> 11;

    const int tid   = threadIdx.x;         // 0..511
    const int rsub  = tid >> 8;            // row within pair
    const int t256  = tid & 255;
    const int half  = t256 >> 7;           // 0 = left, 1 = right
    const int dhalf = (t256 >> 6) & 1;     // d block
    const int l64   = t256 & 63;           // float4 column
    const int w4    = l64 << 2;
    const int d0    = dhalf << 4;          // 0 or 16
    const int h     = hp * 2 + rsub;

    const size_t in_off = ((((size_t)b * C + c) * H) + h) * W;

    // ---- stage row pair + zero pads (per 256-thread group) ----
    if (t256 < 64) {
        slbuf[rsub][t256] = reinterpret_cast<const float4*>(left + in_off)[t256];
    } else if (t256 < 128) {
        srbuf[rsub][8 + (t256 - 64)] =
            reinterpret_cast<const float4*>(right + in_off)[t256 - 64];
    } else if (t256 < 136) {
        slbuf[rsub][64 + (t256 - 128)] = make_float4(0.f, 0.f, 0.f, 0.f);
    } else if (t256 < 144) {
        srbuf[rsub][t256 - 136] = make_float4(0.f, 0.f, 0.f, 0.f);
    }
    __syncthreads();

    // ---- 20-float register window (5 x LDS.128) ----
    // Left  thread: f[k] = left_row [w4 + d0 + k],      k = 0..19
    // Right thread: f[k] = right_row[w4 - d0 - 16 + k], k = 0..19
    float f[20];
    {
        const float4* buf  = half ? srbuf[rsub] : slbuf[rsub];
        const int     base = half ? (l64 + 4 - 4 * dhalf) : (l64 + 4 * dhalf);
        #pragma unroll
        for (int i = 0; i < 5; i++) {
            float4 q = buf[base + i];
            f[4 * i + 0] = q.x;
            f[4 * i + 1] = q.y;
            f[4 * i + 2] = q.z;
            f[4 * i + 3] = q.w;
        }
    }

    // ---- emit 16 disparity planes (one uninterrupted streaming burst) ----
    const size_t dstride = (size_t)H * W;  // 32768 floats per d-plane
    float* dst = out
        + ((size_t)(b * 2 * C + half * C + c) * D + d0) * dstride
        + (size_t)h * W + w4;

    if (half == 0) {
        // d = d0 + dd: out = left_row[w4+d .. w4+d+3] = f[dd .. dd+3]
        #pragma unroll
        for (int dd = 0; dd < 16; dd++) {
            float4 v = make_float4(f[dd], f[dd + 1], f[dd + 2], f[dd + 3]);
            stcs128(dst + (size_t)dd * dstride, v);
        }
    } else {
        // d = d0 + dd: out = right_row[w4-d .. w4-d+3] = f[16-dd .. 19-dd]
        #pragma unroll
        for (int dd = 0; dd < 16; dd++) {
            float4 v = make_float4(f[16 - dd], f[17 - dd], f[18 - dd], f[19 - dd]);
            stcs128(dst + (size_t)dd * dstride, v);
        }
    }
}

extern "C" void kernel_launch(void* const* d_in, const int* in_sizes, int n_in,
                              void* d_out, int out_size) {
    const float* left  = (const float*)d_in[0];
    const float* right = (const float*)d_in[1];
    float* out = (float*)d_out;

    (void)in_sizes; (void)n_in; (void)out_size;

    const int grid = B * C * (H / 2);  // 4096 CTAs
    cost_volume_kernel<<<grid, 512>>>(left, right, out);
}